// round 11
// baseline (speedup 1.0000x reference)
#include <cuda_runtime.h>
#include <cuda_fp16.h>
#include <cstdint>

#define T_TOK 8192
#define HID   2048
#define OUTC  3072
#define ACOLS 384
#define KEXT  2176        // HID + 128 appended rank-block
#define BM 128
#define BN 128
#define NB0 3             // GEMM0 N-tiles (384/128)
#define NB1 24            // GEMM1 N-tiles (3072/128)
#define MBLK 64           // row blocks (8192/128)

// ---------------- scratch (device globals; no runtime alloc) ----------------
__device__ __align__(128) __half g_xf[(size_t)T_TOK*HID];
__device__ __align__(128) __half g_w2[(size_t)OUTC*KEXT];      // [W | Ball_g]
__device__ __align__(128) __half g_ac[(size_t)ACOLS*HID];      // A_cat 384x2048
__device__ __align__(128) __half g_h2[(size_t)T_TOK*ACOLS];
__device__ int g_done[MBLK];
__device__ int g_is64;

#define DINL __device__ __forceinline__

DINL uint32_t smem_u32(const void* p){ uint32_t a;
  asm("{ .reg .u64 t; cvta.to.shared.u64 t, %1; cvt.u32.u64 %0, t; }":"=r"(a):"l"(p)); return a; }

DINL uint32_t swz(uint32_t off){ return off ^ ((off>>3)&0x70); }

DINL void ldmx4(uint32_t* r, uint32_t addr){
  asm volatile("ldmatrix.sync.aligned.m8n8.x4.shared.b16 {%0,%1,%2,%3}, [%4];"
    : "=r"(r[0]),"=r"(r[1]),"=r"(r[2]),"=r"(r[3]) : "r"(addr));
}

DINL void mma16816(float* c, const uint32_t* a, const uint32_t* b){
  asm volatile("mma.sync.aligned.m16n8k16.row.col.f32.f16.f16.f32 "
    "{%0,%1,%2,%3},{%4,%5,%6,%7},{%8,%9},{%0,%1,%2,%3};"
    : "+f"(c[0]),"+f"(c[1]),"+f"(c[2]),"+f"(c[3])
    : "r"(a[0]),"r"(a[1]),"r"(a[2]),"r"(a[3]),"r"(b[0]),"r"(b[1]));
}

#define CPA_COMMIT() asm volatile("cp.async.commit_group;\n":::"memory")
#define CPA_WAIT1()  asm volatile("cp.async.wait_group 1;\n":::"memory")

// load 128 x 64 fp16 (128B rows) into SW128-swizzled SMEM via cp.async; 128 threads
DINL void load_tile(uint32_t dst, const __half* g, long rowBase, int ld, int k0, int tid){
  const char* s0 = (const char*)(g + rowBase*(long)ld + k0);
  const long rb = (long)ld*2;
  #pragma unroll
  for(int c=tid; c<128*8; c+=128){
    int row=c>>3, ck=c&7;
    uint32_t off=(uint32_t)(row*128+ck*16);
    const void* src = s0 + (long)row*rb + ck*16;
    asm volatile("cp.async.cg.shared.global [%0], [%1], 16;\n"::"r"(dst+swz(off)),"l"(src):"memory");
  }
}

static constexpr uint32_t TILE_B = 128*128;        // 16 KB per tile
static constexpr uint32_t STAGE  = 2*TILE_B;       // A + B = 32 KB
static constexpr int      NSTG   = 3;
static constexpr uint32_t SMEM_TOTAL = NSTG*STAGE; // 96 KB -> 2 CTAs/SM

// Fused kernel: blocks [0,192) = GEMM0 (H2 = mask/scale(X @ A_cat^T)),
// blocks [192,1728) = GEMM1 (out = [X | H2_g] @ [W | Ball_g]^T, K=2176).
// GEMM1 CTAs wait on g_done[rowblock]==3 before prefetching H2 K-iters.
__global__ void __launch_bounds__(128,2)
gemm_fused(const __half* __restrict__ X,
           const __half* __restrict__ AC,
           const __half* __restrict__ W2,
           const __half* __restrict__ H2rw,   // same buffer, written by GEMM0, read by GEMM1
           float* __restrict__ out,
           const unsigned int* __restrict__ tts, const float* __restrict__ scal){
  extern __shared__ __align__(1024) char smem[];
  const uint32_t sb = smem_u32(smem);
  const int tid=threadIdx.x, lane=tid&31, wid=tid>>5;
  const int wm=wid>>1, wn=wid&1;                 // 2x2 warp grid -> m64 x n64 warp tile

  const int bid = blockIdx.x;
  const bool is0 = (bid < NB0*MBLK);
  int bx, by;
  if(is0){ bx = bid % NB0; by = bid / NB0; }
  else   { int b = bid - NB0*MBLK; bx = b % NB1; by = b / NB1; }
  const long mB=(long)by*BM, nB=(long)bx*BN;
  const int NK  = is0 ? (HID/64) : (KEXT/64);    // 32 : 34
  const int nkx = HID/64;                         // 32
  const int gofs = is0 ? 0 : ((nB>=2560)?256:((nB>=2048)?128:0));
  const __half* Bmat = is0 ? AC : W2;
  const int ldb = is0 ? HID : KEXT;

  auto st=[&](int s){ return sb + (uint32_t)s*STAGE; };
  auto load_st=[&](int s,int ki){
    uint32_t a=st(s);
    if(!is0 && ki>=nkx) load_tile(a, H2rw, mB, ACOLS, gofs + (ki-nkx)*64, tid);
    else                load_tile(a, X,    mB, HID,   ki*64, tid);
    load_tile(a+TILE_B, Bmat, nB, ldb, ki*64, tid);
  };

  float c[4][8][4];
  #pragma unroll
  for(int i=0;i<4;i++)
    #pragma unroll
    for(int j=0;j<8;j++)
      #pragma unroll
      for(int e=0;e<4;e++) c[i][j][e]=0.f;

  const int rowA = (lane&15);
  const int cA   = (lane>>4);
  const int rowB = (lane&7) + ((lane>>4)&1)*8;
  const int cB   = (lane>>3)&1;

  // one kk sub-step: 8 LDSM + 32 MMA (m64 x n64 x k16)
  auto process_kk=[&](uint32_t a0, int kk){
    uint32_t af[4][4], bf[8][2];
    #pragma unroll
    for(int mt=0; mt<4; mt++){
      uint32_t off=(uint32_t)((wm*64+mt*16+rowA)*128 + (kk*2+cA)*16);
      ldmx4(af[mt], a0 + swz(off));
    }
    #pragma unroll
    for(int p=0; p<4; p++){
      uint32_t off=(uint32_t)((wn*64+p*16+rowB)*128 + (kk*2+cB)*16);
      uint32_t t[4];
      ldmx4(t, a0 + TILE_B + swz(off));
      bf[2*p][0]=t[0]; bf[2*p][1]=t[1]; bf[2*p+1][0]=t[2]; bf[2*p+1][1]=t[3];
    }
    #pragma unroll
    for(int nt=0; nt<8; nt++)
      #pragma unroll
      for(int mt=0; mt<4; mt++) mma16816(c[mt][nt], af[mt], bf[nt]);
  };

  // prologue: 2 stages in flight
  load_st(0,0); CPA_COMMIT();
  load_st(1,1); CPA_COMMIT();

  #pragma unroll 1
  for(int ki=0; ki<NK; ki++){
    CPA_WAIT1();
    __syncthreads();
    const uint32_t a0 = st(ki%NSTG);
    process_kk(a0, 0);                       // tensor starts right after barrier
    // GEMM1: before prefetching the first H2 stage, wait for this row-block's H2
    if(!is0 && ki+2==nkx){
      if(tid==0){ while(atomicAdd(&g_done[by],0) < NB0) { } }
      __syncthreads();
      __threadfence();
    }
    if(ki+2<NK) load_st((ki+2)%NSTG, ki+2);  // deferred prefetch overlaps MMAs
    CPA_COMMIT();
    process_kk(a0, 1);
    process_kk(a0, 2);
    process_kk(a0, 3);
  }

  // ------------- epilogue -------------
  const int r0 = wm*64 + (lane>>2);
  const int cc0 = wn*64 + (lane&3)*2;
  if(is0){
    __half* h2 = (__half*)H2rw;
    #pragma unroll
    for(int mt=0; mt<4; mt++)
      #pragma unroll
      for(int h=0; h<2; h++){
        long row = mB + r0 + mt*16 + h*8;
        int slot = g_is64 ? (int)tts[2*row] : (int)tts[row];
        float sc = scal[slot];
        #pragma unroll
        for(int nt=0; nt<8; nt++){
          int a = (int)nB + cc0 + nt*8;
          int l = (a>>4)&7;
          float v0 = (l==slot)? sc*c[mt][nt][h*2]   : 0.f;
          float v1 = (l==slot)? sc*c[mt][nt][h*2+1] : 0.f;
          *(__half2*)(h2 + row*ACOLS + a) = __floats2half2_rn(v0, v1);
        }
      }
    __threadfence();
    __syncthreads();
    if(tid==0) atomicAdd(&g_done[by], 1);
  } else {
    #pragma unroll
    for(int mt=0; mt<4; mt++)
      #pragma unroll
      for(int h=0; h<2; h++){
        long row = mB + r0 + mt*16 + h*8;
        float2* base=(float2*)(out + row*OUTC + nB + cc0);
        #pragma unroll
        for(int nt=0; nt<8; nt++)
          base[nt*4] = make_float2(c[mt][nt][h*2], c[mt][nt][h*2+1]);
      }
  }
}

// ---------------- prep kernels ----------------
// fp32 -> fp16 convert; block 0 additionally sniffs token_to_slot dtype + zeroes flags
__global__ void k_cvt_x(const float* __restrict__ x, __half* __restrict__ xf, int n4,
                        const unsigned int* __restrict__ tts){
  int i=blockIdx.x*blockDim.x+threadIdx.x;
  if(i<n4){
    float4 v=((const float4*)x)[i];
    ((__half2*)xf)[2*i]  =__floats2half2_rn(v.x,v.y);
    ((__half2*)xf)[2*i+1]=__floats2half2_rn(v.z,v.w);
  }
  if(blockIdx.x==0){
    if(threadIdx.x < MBLK) g_done[threadIdx.x] = 0;
    __shared__ int found;
    if(threadIdx.x==0) found=0;
    __syncthreads();
    int loc=0;
    for(int j=1+2*(int)threadIdx.x; j<T_TOK; j+=512) loc|=(tts[j]!=0u);
    if(loc) atomicOr(&found,1);
    __syncthreads();
    if(threadIdx.x==0) g_is64 = found?0:1;
  }
}

// blocks [0,OUTC): one W2 row; blocks [OUTC,OUTC+ACOLS): one A_cat row
__global__ void k_build_w2(const float* __restrict__ w, const float* __restrict__ bq,
                           const float* __restrict__ bk, const float* __restrict__ bv,
                           const float* __restrict__ la,
                           __half* __restrict__ w2, __half* __restrict__ ac){
  const int blk = blockIdx.x;
  const int tid = threadIdx.x;
  if(blk < OUTC){
    const int row = blk;
    const float4* src = (const float4*)(w + (long)row*HID);
    __half2* dst = (__half2*)(w2 + (long)row*KEXT);
    #pragma unroll
    for(int k4 = tid; k4 < HID/4; k4 += 256){
      float4 v = src[k4];
      dst[2*k4]   = __floats2half2_rn(v.x, v.y);
      dst[2*k4+1] = __floats2half2_rn(v.z, v.w);
    }
    if(tid < 128){
      int l = tid>>4, r = tid&15;
      float v;
      if(row<2048)      v=bq[((long)l*2048+row)*16+r];
      else if(row<2560) v=bk[((long)l*512+(row-2048))*16+r];
      else              v=bv[((long)l*512+(row-2560))*16+r];
      w2[(long)row*KEXT + HID + tid] = __float2half_rn(v);
    }
  } else {
    const int a = blk - OUTC;              // a = g*128 + l*16 + r
    int g=a>>7, l=(a>>4)&7, r=a&15;
    const float4* src = (const float4*)(la + (((long)l*3+g)*16+r)*HID);
    __half2* dst = (__half2*)(ac + (long)a*HID);
    #pragma unroll
    for(int k4 = tid; k4 < HID/4; k4 += 256){
      float4 v = src[k4];
      dst[2*k4]   = __floats2half2_rn(v.x, v.y);
      dst[2*k4+1] = __floats2half2_rn(v.z, v.w);
    }
  }
}

extern "C" void kernel_launch(void* const* d_in, const int* in_sizes, int n_in,
                              void* d_out, int out_size){
  (void)in_sizes; (void)n_in; (void)out_size;
  const float* x =(const float*)d_in[0];
  const float* w =(const float*)d_in[1];
  const float* la=(const float*)d_in[2];
  const float* bq=(const float*)d_in[3];
  const float* bk=(const float*)d_in[4];
  const float* bv=(const float*)d_in[5];
  const float* sc=(const float*)d_in[6];
  const unsigned int* tt=(const unsigned int*)d_in[7];
  float* out=(float*)d_out;

  void *xf,*w2,*ac,*h2;
  cudaGetSymbolAddress(&xf,g_xf); cudaGetSymbolAddress(&w2,g_w2);
  cudaGetSymbolAddress(&ac,g_ac); cudaGetSymbolAddress(&h2,g_h2);

  cudaFuncSetAttribute((const void*)gemm_fused, cudaFuncAttributeMaxDynamicSharedMemorySize, SMEM_TOTAL);

  // launch 1: convert X (+dtype sniff, flag reset)
  k_cvt_x<<<(T_TOK*HID/4+255)/256,256>>>(x,(__half*)xf,T_TOK*HID/4,tt);
  // launch 2: build W2 and A_cat
  k_build_w2<<<OUTC+ACOLS,256>>>(w,bq,bk,bv,la,(__half*)w2,(__half*)ac);

  // launch 3 — fused GEMM0 + GEMM1 (1728 CTAs; GEMM0 first in schedule order)
  gemm_fused<<<NB0*MBLK + NB1*MBLK, 128, SMEM_TOTAL>>>(
      (const __half*)xf, (const __half*)ac, (const __half*)w2, (const __half*)h2,
      out, tt, sc);
}

// round 13
// speedup vs baseline: 1.5230x; 1.5230x over previous
#include <cuda_runtime.h>
#include <cuda_fp16.h>
#include <cstdint>

#define T_TOK 8192
#define HID   2048
#define OUTC  3072
#define ACOLS 384
#define KEXT  2176        // HID + 128 appended rank-block
#define BM 128
#define BN 128
#define NB0 3             // GEMM0 N-tiles (384/128)
#define NB1 24            // GEMM1 N-tiles (3072/128)
#define MBLK 64           // row blocks (8192/128)
#define NCVT 16384        // conversion blocks in prep (8192*2048/4 float4 / 256 thr)

// ---------------- scratch (device globals; no runtime alloc) ----------------
__device__ __align__(128) __half g_xf[(size_t)T_TOK*HID];
__device__ __align__(128) __half g_w2[(size_t)OUTC*KEXT];      // [W | Ball_g]
__device__ __align__(128) __half g_ac[(size_t)ACOLS*HID];      // A_cat 384x2048
__device__ __align__(128) __half g_h2[(size_t)T_TOK*ACOLS];
__device__ int g_done[MBLK];
__device__ int g_is64;

#define DINL __device__ __forceinline__

DINL uint32_t smem_u32(const void* p){ uint32_t a;
  asm("{ .reg .u64 t; cvta.to.shared.u64 t, %1; cvt.u32.u64 %0, t; }":"=r"(a):"l"(p)); return a; }

DINL uint32_t swz(uint32_t off){ return off ^ ((off>>3)&0x70); }

DINL void ldmx4(uint32_t* r, uint32_t addr){
  asm volatile("ldmatrix.sync.aligned.m8n8.x4.shared.b16 {%0,%1,%2,%3}, [%4];"
    : "=r"(r[0]),"=r"(r[1]),"=r"(r[2]),"=r"(r[3]) : "r"(addr));
}

DINL void mma16816(float* c, const uint32_t* a, const uint32_t* b){
  asm volatile("mma.sync.aligned.m16n8k16.row.col.f32.f16.f16.f32 "
    "{%0,%1,%2,%3},{%4,%5,%6,%7},{%8,%9},{%0,%1,%2,%3};"
    : "+f"(c[0]),"+f"(c[1]),"+f"(c[2]),"+f"(c[3])
    : "r"(a[0]),"r"(a[1]),"r"(a[2]),"r"(a[3]),"r"(b[0]),"r"(b[1]));
}

#define CPA_COMMIT() asm volatile("cp.async.commit_group;\n":::"memory")
#define CPA_WAIT1()  asm volatile("cp.async.wait_group 1;\n":::"memory")

// load 128 x 64 fp16 (128B rows) into SW128-swizzled SMEM via cp.async; 256 threads
DINL void load_tile(uint32_t dst, const __half* g, long rowBase, int ld, int k0, int tid){
  const char* s0 = (const char*)(g + rowBase*(long)ld + k0);
  const long rb = (long)ld*2;
  #pragma unroll
  for(int c=tid; c<128*8; c+=256){
    int row=c>>3, ck=c&7;
    uint32_t off=(uint32_t)(row*128+ck*16);
    const void* src = s0 + (long)row*rb + ck*16;
    asm volatile("cp.async.cg.shared.global [%0], [%1], 16;\n"::"r"(dst+swz(off)),"l"(src):"memory");
  }
}

static constexpr uint32_t TILE_B = 128*128;        // 16 KB per tile
static constexpr uint32_t STAGE  = 2*TILE_B;       // A + B = 32 KB
static constexpr int      NSTG   = 3;
static constexpr uint32_t SMEM_TOTAL = NSTG*STAGE; // 96 KB -> 2 CTAs/SM

// Fused kernel on the R8 body (256 thr, 2x4 warp grid, warp tile m64 x n32, regs~128):
// blocks [0,192)       : GEMM0 -> H2 = mask/scale(X @ A_cat^T)   (K=2048)
// blocks [192,1728)    : GEMM1 -> out = [X | H2_g] @ [W | Ball_g]^T (K=2176)
// GEMM1 CTAs spin once on g_done[rowblock]==3 before prefetching H2 stages.
__global__ void __launch_bounds__(256,2)
gemm_fused(const __half* __restrict__ X,
           const __half* __restrict__ AC,
           const __half* __restrict__ W2,
           const __half* __restrict__ H2rw,
           float* __restrict__ out,
           const unsigned int* __restrict__ tts, const float* __restrict__ scal){
  extern __shared__ __align__(1024) char smem[];
  const uint32_t sb = smem_u32(smem);
  const int tid=threadIdx.x, lane=tid&31, wid=tid>>5;
  const int wm=wid>>2, wn=wid&3;                 // 2 x 4 warp grid -> m64 x n32 warp tile

  const int bid = blockIdx.x;
  const bool is0 = (bid < NB0*MBLK);
  int bx, by;
  if(is0){ bx = bid % NB0; by = bid / NB0; }
  else   { int b = bid - NB0*MBLK; bx = b % NB1; by = b / NB1; }
  const long mB=(long)by*BM, nB=(long)bx*BN;
  const int NK  = is0 ? (HID/64) : (KEXT/64);    // 32 : 34
  constexpr int nkx = HID/64;                    // 32
  const int gofs = is0 ? 0 : ((nB>=2560)?256:((nB>=2048)?128:0));
  const __half* Bmat = is0 ? AC : W2;
  const int ldb = is0 ? HID : KEXT;

  auto st=[&](int s){ return sb + (uint32_t)s*STAGE; };
  auto load_st=[&](int s,int ki){
    uint32_t a=st(s);
    if(!is0 && ki>=nkx) load_tile(a, H2rw, mB, ACOLS, gofs + (ki-nkx)*64, tid);
    else                load_tile(a, X,    mB, HID,   ki*64, tid);
    load_tile(a+TILE_B, Bmat, nB, ldb, ki*64, tid);
  };

  float c[4][4][4];
  #pragma unroll
  for(int i=0;i<4;i++)
    #pragma unroll
    for(int j=0;j<4;j++)
      #pragma unroll
      for(int e=0;e<4;e++) c[i][j][e]=0.f;

  const int rowA = (lane&15);
  const int cA   = (lane>>4);
  const int rowB = (lane&7) + ((lane>>4)&1)*8;
  const int cB   = (lane>>3)&1;

  // one kk sub-step: 6 LDSM + 16 MMA (m64 x n32 x k16)
  auto process_kk=[&](uint32_t a0, int kk){
    uint32_t af[4][4], bf[4][2];
    #pragma unroll
    for(int mt=0; mt<4; mt++){
      uint32_t off=(uint32_t)((wm*64+mt*16+rowA)*128 + (kk*2+cA)*16);
      ldmx4(af[mt], a0 + swz(off));
    }
    #pragma unroll
    for(int p=0; p<2; p++){
      uint32_t off=(uint32_t)((wn*32+p*16+rowB)*128 + (kk*2+cB)*16);
      uint32_t t[4];
      ldmx4(t, a0 + TILE_B + swz(off));
      bf[2*p][0]=t[0]; bf[2*p][1]=t[1]; bf[2*p+1][0]=t[2]; bf[2*p+1][1]=t[3];
    }
    #pragma unroll
    for(int nt=0; nt<4; nt++)
      #pragma unroll
      for(int mt=0; mt<4; mt++) mma16816(c[mt][nt], af[mt], bf[nt]);
  };

  // prologue: 2 stages in flight
  load_st(0,0); CPA_COMMIT();
  load_st(1,1); CPA_COMMIT();

  #pragma unroll 1
  for(int ki=0; ki<NK; ki++){
    CPA_WAIT1();
    __syncthreads();
    const uint32_t a0 = st(ki%NSTG);
    process_kk(a0, 0);                       // tensor starts right after barrier
    // GEMM1: one-time wait for this row-block's H2 before its first H2 prefetch
    if(!is0 && ki+2==nkx){
      if(tid==0){ while(atomicAdd(&g_done[by],0) < NB0) { } }
      __syncthreads();
      __threadfence();
    }
    if(ki+2<NK) load_st((ki+2)%NSTG, ki+2);  // deferred prefetch overlaps MMAs
    CPA_COMMIT();
    process_kk(a0, 1);
    process_kk(a0, 2);
    process_kk(a0, 3);
  }

  // ------------- epilogue -------------
  const int r0 = wm*64 + (lane>>2);
  const int cc0 = wn*32 + (lane&3)*2;
  if(is0){
    __half* h2 = (__half*)H2rw;
    #pragma unroll
    for(int mt=0; mt<4; mt++)
      #pragma unroll
      for(int h=0; h<2; h++){
        long row = mB + r0 + mt*16 + h*8;
        int slot = g_is64 ? (int)tts[2*row] : (int)tts[row];
        float sc = scal[slot];
        #pragma unroll
        for(int nt=0; nt<4; nt++){
          int a = (int)nB + cc0 + nt*8;
          int l = (a>>4)&7;
          float v0 = (l==slot)? sc*c[mt][nt][h*2]   : 0.f;
          float v1 = (l==slot)? sc*c[mt][nt][h*2+1] : 0.f;
          *(__half2*)(h2 + row*ACOLS + a) = __floats2half2_rn(v0, v1);
        }
      }
    __threadfence();
    __syncthreads();
    if(tid==0) atomicAdd(&g_done[by], 1);
  } else {
    #pragma unroll
    for(int mt=0; mt<4; mt++)
      #pragma unroll
      for(int h=0; h<2; h++){
        long row = mB + r0 + mt*16 + h*8;
        float2* base=(float2*)(out + row*OUTC + nB + cc0);
        #pragma unroll
        for(int nt=0; nt<4; nt++)
          base[nt*4] = make_float2(c[mt][nt][h*2], c[mt][nt][h*2+1]);
      }
  }
}

// ---------------- merged prep: cvt X + build W2 + build A_cat + flag reset ----------------
__global__ void k_prep(const float* __restrict__ x, __half* __restrict__ xf,
                       const unsigned int* __restrict__ tts,
                       const float* __restrict__ w, const float* __restrict__ bq,
                       const float* __restrict__ bk, const float* __restrict__ bv,
                       const float* __restrict__ la,
                       __half* __restrict__ w2, __half* __restrict__ ac){
  const int blk = blockIdx.x;
  const int tid = threadIdx.x;
  if(blk < NCVT){
    int i = blk*256 + tid;                    // i < 8192*2048/4
    float4 v=((const float4*)x)[i];
    ((__half2*)xf)[2*i]  =__floats2half2_rn(v.x,v.y);
    ((__half2*)xf)[2*i+1]=__floats2half2_rn(v.z,v.w);
    if(blk==0){
      if(tid < MBLK) g_done[tid] = 0;
      __shared__ int found;
      if(tid==0) found=0;
      __syncthreads();
      int loc=0;
      for(int j=1+2*tid; j<T_TOK; j+=512) loc|=(tts[j]!=0u);
      if(loc) atomicOr(&found,1);
      __syncthreads();
      if(tid==0) g_is64 = found?0:1;
    }
  } else if(blk < NCVT + OUTC){
    const int row = blk - NCVT;
    const float4* src = (const float4*)(w + (long)row*HID);
    __half2* dst = (__half2*)(w2 + (long)row*KEXT);
    #pragma unroll
    for(int k4 = tid; k4 < HID/4; k4 += 256){
      float4 v = src[k4];
      dst[2*k4]   = __floats2half2_rn(v.x, v.y);
      dst[2*k4+1] = __floats2half2_rn(v.z, v.w);
    }
    if(tid < 128){
      int l = tid>>4, r = tid&15;
      float v;
      if(row<2048)      v=bq[((long)l*2048+row)*16+r];
      else if(row<2560) v=bk[((long)l*512+(row-2048))*16+r];
      else              v=bv[((long)l*512+(row-2560))*16+r];
      w2[(long)row*KEXT + HID + tid] = __float2half_rn(v);
    }
  } else {
    const int a = blk - NCVT - OUTC;          // a = g*128 + l*16 + r
    int g=a>>7, l=(a>>4)&7, r=a&15;
    const float4* src = (const float4*)(la + (((long)l*3+g)*16+r)*HID);
    __half2* dst = (__half2*)(ac + (long)a*HID);
    #pragma unroll
    for(int k4 = tid; k4 < HID/4; k4 += 256){
      float4 v = src[k4];
      dst[2*k4]   = __floats2half2_rn(v.x, v.y);
      dst[2*k4+1] = __floats2half2_rn(v.z, v.w);
    }
  }
}

extern "C" void kernel_launch(void* const* d_in, const int* in_sizes, int n_in,
                              void* d_out, int out_size){
  (void)in_sizes; (void)n_in; (void)out_size;
  const float* x =(const float*)d_in[0];
  const float* w =(const float*)d_in[1];
  const float* la=(const float*)d_in[2];
  const float* bq=(const float*)d_in[3];
  const float* bk=(const float*)d_in[4];
  const float* bv=(const float*)d_in[5];
  const float* sc=(const float*)d_in[6];
  const unsigned int* tt=(const unsigned int*)d_in[7];
  float* out=(float*)d_out;

  void *xf,*w2,*ac,*h2;
  cudaGetSymbolAddress(&xf,g_xf); cudaGetSymbolAddress(&w2,g_w2);
  cudaGetSymbolAddress(&ac,g_ac); cudaGetSymbolAddress(&h2,g_h2);

  cudaFuncSetAttribute((const void*)gemm_fused, cudaFuncAttributeMaxDynamicSharedMemorySize, SMEM_TOTAL);

  // launch 1: merged prep (cvt X + W2 + A_cat + flag reset + dtype sniff)
  k_prep<<<NCVT + OUTC + ACOLS, 256>>>(x,(__half*)xf,tt,w,bq,bk,bv,la,(__half*)w2,(__half*)ac);

  // launch 2: fused GEMM0 + GEMM1 (GEMM0 CTAs first in schedule order)
  gemm_fused<<<NB0*MBLK + NB1*MBLK, 256, SMEM_TOTAL>>>(
      (const __half*)xf, (const __half*)ac, (const __half*)w2, (const __half*)h2,
      out, tt, sc);
}